// round 1
// baseline (speedup 1.0000x reference)
#include <cuda_runtime.h>
#include <math.h>

// Problem constants
#define Bn   16
#define Cn   256
#define Hn   48
#define Wn   48
#define HWn  2304          // 48*48
#define NG   40            // 8 + 16 + 16 basis functions total
#define KK   49            // 7*7

// Scratch (device globals: allocation-free rule)
__device__ float g_z[Bn * Cn];                 // GAP          [B, C]
__device__ float g_fs[Bn * HWn];               // channel sum  [B, H, W]
__device__ float g_h[3 * Bn * 64];             // MLP hidden   [br, B, 64]
__device__ float g_coeff[Bn * NG * Cn];        // coeffs       [B, nG, C]
__device__ float g_basis[NG * KK];             // bases        [nG, 49]
__device__ float g_G[3 * Bn * 256];            // Gram/C       [br, B, N*N]
__device__ float g_s1[3 * Bn * 16];            // colmean      [br, B, N]
__device__ float g_U[Bn * NG * HWn];           // basis convs  [B, nG, HW]

// ---------------------------------------------------------------------------
// k0: zero fs (atomics target)
__global__ void k_zero() {
    int i = blockIdx.x * 256 + threadIdx.x;
    if (i < Bn * HWn) g_fs[i] = 0.f;
}

// ---------------------------------------------------------------------------
// k1: fused reduction — z[b,c] = mean_HW(feature), fs[b,p] = sum_C(feature)
// grid (16 chunks of 16 channels, B), block 256
__global__ void k_reduce(const float* __restrict__ feat) {
    int b = blockIdx.y, chunk = blockIdx.x;
    int tid = threadIdx.x;
    int lane = tid & 31, wid = tid >> 5;
    __shared__ float zsum[16][8];

    float facc[9];
#pragma unroll
    for (int k = 0; k < 9; ++k) facc[k] = 0.f;

    const float* fb = feat + ((size_t)b * Cn + (size_t)chunk * 16) * HWn;
    for (int c = 0; c < 16; ++c) {
        const float* fp = fb + (size_t)c * HWn;
        float csum = 0.f;
#pragma unroll
        for (int k = 0; k < 9; ++k) {
            float v = fp[tid + 256 * k];
            facc[k] += v;
            csum += v;
        }
#pragma unroll
        for (int o = 16; o; o >>= 1) csum += __shfl_xor_sync(0xffffffffu, csum, o);
        if (lane == 0) zsum[c][wid] = csum;
    }
    __syncthreads();
    if (tid < 16) {
        float s = 0.f;
#pragma unroll
        for (int w = 0; w < 8; ++w) s += zsum[tid][w];
        g_z[b * Cn + chunk * 16 + tid] = s * (1.f / (float)HWn);
    }
#pragma unroll
    for (int k = 0; k < 9; ++k)
        atomicAdd(&g_fs[b * HWn + tid + 256 * k], facc[k]);
}

// ---------------------------------------------------------------------------
// k2: compute all 40 basis kernels (gaussian-derivative + circular harmonics)
__global__ void k_basis(const float* __restrict__ rw1, const float* __restrict__ rb1,
                        const float* __restrict__ rw2, const float* __restrict__ rb2) {
    __shared__ float r[KK], th[KK];
    int tid = threadIdx.x;
    if (tid < KK) {
        int i = tid / 7, j = tid % 7;
        float gy = (float)i - 3.f, gx = (float)j - 3.f;
        r[tid] = sqrtf(gx * gx + gy * gy + 1e-8f);
        th[tid] = atan2f(gy, gx);
    }
    __syncthreads();

    // Gaussian bases: inv (threads 0..7), eq (threads 8..23)
    if (tid < 24) {
        bool inv = tid < 8;
        int i = inv ? tid : (tid - 8);
        int combo = i % 9;
        int d = combo / 3, si = combo % 3;
        float sig = inv ? (4.f + 2.f * (float)si) : (1.f + (float)si);
        float psi[KK];
        float ss = 0.f;
        for (int c = 0; c < KK; ++c) {
            float u = r[c] / sig;
            float g = expf(-0.5f * u * u);
            float p = (d == 0) ? 1.f : ((d == 1) ? u : (u * u - 1.f));
            psi[c] = p * g;
            ss += psi[c] * psi[c];
        }
        float inorm = 1.f / sqrtf(ss + 1e-8f);
        int gi = inv ? tid : (8 + i);
        for (int c = 0; c < KK; ++c) g_basis[gi * KK + c] = psi[c] * inorm;
    }

    // Harmonic bases: one thread per cell
    if (tid < KK) {
        float rad0 = rb2[0], rad1 = rb2[1];
        for (int h = 0; h < 32; ++h) {
            float t = tanhf(r[tid] * rw1[h] + rb1[h]);
            rad0 += t * rw2[h * 2 + 0];
            rad1 += t * rw2[h * 2 + 1];
        }
        for (int l = 0; l < 8; ++l) {
            float o = (float)(l / 2 + 1);
            float a = (l & 1) ? sinf(o * th[tid]) : cosf(o * th[tid]);
            g_basis[(24 + l) * KK + tid] = rad0 * a;
            g_basis[(24 + 8 + l) * KK + tid] = rad1 * a;
        }
    }
}

// ---------------------------------------------------------------------------
// k3: hidden layer h = relu(z @ w1 + b1), per branch. grid (B, 3), block 64
__global__ void k_hid(const float* __restrict__ w1i, const float* __restrict__ b1i,
                      const float* __restrict__ w1e, const float* __restrict__ b1e,
                      const float* __restrict__ w1c, const float* __restrict__ b1c) {
    int b = blockIdx.x, br = blockIdx.y, j = threadIdx.x;
    const float* w1 = (br == 0) ? w1i : ((br == 1) ? w1e : w1c);
    const float* b1 = (br == 0) ? b1i : ((br == 1) ? b1e : b1c);
    const float* z = g_z + b * Cn;
    float acc = b1[j];
    for (int c = 0; c < Cn; ++c) acc += z[c] * w1[c * 64 + j];
    g_h[(br * Bn + b) * 64 + j] = fmaxf(acc, 0.f);
}

// ---------------------------------------------------------------------------
// k4: coeff = h @ w2 + b2. grid (40, B), block 256 (thread = c)
__global__ void k_coeff(const float* __restrict__ w2i, const float* __restrict__ b2i,
                        const float* __restrict__ w2e, const float* __restrict__ b2e,
                        const float* __restrict__ w2c, const float* __restrict__ b2c) {
    int nG = blockIdx.x, b = blockIdx.y, c = threadIdx.x;
    int br, n, NC;
    if (nG < 8)       { br = 0; n = nG;      NC = 8 * Cn;  }
    else if (nG < 24) { br = 1; n = nG - 8;  NC = 16 * Cn; }
    else              { br = 2; n = nG - 24; NC = 16 * Cn; }
    const float* w2 = (br == 0) ? w2i : ((br == 1) ? w2e : w2c);
    const float* b2 = (br == 0) ? b2i : ((br == 1) ? b2e : b2c);

    __shared__ float hs[64];
    if (c < 64) hs[c] = g_h[(br * Bn + b) * 64 + c];
    __syncthreads();

    float acc = b2[n * Cn + c];
#pragma unroll 8
    for (int hh = 0; hh < 64; ++hh)
        acc += hs[hh] * w2[(size_t)hh * NC + n * Cn + c];
    g_coeff[((size_t)b * NG + nG) * Cn + c] = acc;
}

// ---------------------------------------------------------------------------
// k5: per (branch, b) stats: column-mean vector (s1/C) and Gram/C
// grid (3, B), block 288
__global__ void k_stats() {
    int br = blockIdx.x, b = blockIdx.y;
    int N = (br == 0) ? 8 : 16;
    int nbase = (br == 0) ? 0 : ((br == 1) ? 8 : 24);
    __shared__ float s[16 * Cn];
    const float* cf = g_coeff + ((size_t)b * NG + nbase) * Cn;
    for (int i = threadIdx.x; i < N * Cn; i += blockDim.x) s[i] = cf[i];
    __syncthreads();
    int tid = threadIdx.x;
    if (tid < N * N) {
        int n = tid / N, m = tid % N;
        float acc = 0.f;
        for (int c = 0; c < Cn; ++c) acc += s[n * Cn + c] * s[m * Cn + c];
        g_G[(br * Bn + b) * 256 + tid] = acc * (1.f / (float)Cn);
    }
    if (tid >= N * N && tid < N * N + N) {
        int n = tid - N * N;
        float acc = 0.f;
        for (int c = 0; c < Cn; ++c) acc += s[n * Cn + c];
        g_s1[(br * Bn + b) * 16 + n] = acc * (1.f / (float)Cn);
    }
}

// ---------------------------------------------------------------------------
// k6: U[b,n,p] = (fs[b] (*) basis[n])[p], pad 3, cross-correlation
// grid (40, B), block 256
__global__ void k_uconv() {
    int n = blockIdx.x, b = blockIdx.y, tid = threadIdx.x;
    __shared__ float fp[54 * 54];
    __shared__ float bs[KK];
    if (tid < KK) bs[tid] = g_basis[n * KK + tid];
    for (int i = tid; i < 54 * 54; i += 256) {
        int row = i / 54, col = i % 54;
        int y = row - 3, x = col - 3;
        fp[i] = (y >= 0 && y < Hn && x >= 0 && x < Wn) ? g_fs[b * HWn + y * Wn + x] : 0.f;
    }
    __syncthreads();
    float* up = g_U + ((size_t)b * NG + n) * HWn;
#pragma unroll
    for (int k = 0; k < 9; ++k) {
        int p = tid + 256 * k;
        int y = p / Wn, x = p % Wn;
        float acc = 0.f;
#pragma unroll
        for (int dy = 0; dy < 7; ++dy)
#pragma unroll
            for (int dx = 0; dx < 7; ++dx)
                acc += fp[(y + dy) * 54 + x + dx] * bs[dy * 7 + dx];
        up[p] = acc;
    }
}

// ---------------------------------------------------------------------------
// k7: main fused GEMM + LayerNorm + store. One pass over the output.
// grid (3 pixel-chunks of 768, B), block 256; each thread owns 3 pixels.
template <int N>
__global__ void k_main(int br, int nbase,
                       const float* __restrict__ lng, const float* __restrict__ lnb,
                       float* __restrict__ out) {
    int chunk = blockIdx.x, b = blockIdx.y, tid = threadIdx.x;
    __shared__ float sc[N * Cn];
    __shared__ float sg[Cn], sb[Cn];
    __shared__ float sG[N * N];
    __shared__ float sm[N];

    const float* cf = g_coeff + ((size_t)b * NG + nbase) * Cn;
    for (int i = tid; i < N * Cn; i += 256) sc[i] = cf[i];
    sg[tid] = lng[tid];
    sb[tid] = lnb[tid];
    if (tid < N * N) sG[tid] = g_G[(br * Bn + b) * 256 + tid];
    if (tid < N) sm[tid] = g_s1[(br * Bn + b) * 16 + tid];
    __syncthreads();

    int p0 = chunk * 768 + tid;
    const float* up = g_U + ((size_t)b * NG + nbase) * HWn;
    float u0[N], u1[N], u2[N];
#pragma unroll
    for (int n = 0; n < N; ++n) {
        u0[n] = up[n * HWn + p0];
        u1[n] = up[n * HWn + p0 + 256];
        u2[n] = up[n * HWn + p0 + 512];
    }
    // channel mean per pixel
    float m0 = 0.f, m1 = 0.f, m2 = 0.f;
#pragma unroll
    for (int n = 0; n < N; ++n) {
        float s = sm[n];
        m0 += s * u0[n]; m1 += s * u1[n]; m2 += s * u2[n];
    }
    // E[x^2] per pixel via Gram quadratic form
    float q0 = 0.f, q1 = 0.f, q2 = 0.f;
#pragma unroll
    for (int n = 0; n < N; ++n) {
        float t0 = 0.f, t1 = 0.f, t2 = 0.f;
#pragma unroll
        for (int m = 0; m < N; ++m) {
            float gg = sG[n * N + m];
            t0 += gg * u0[m]; t1 += gg * u1[m]; t2 += gg * u2[m];
        }
        q0 += t0 * u0[n]; q1 += t1 * u1[n]; q2 += t2 * u2[n];
    }
    float r0 = rsqrtf(fmaxf(q0 - m0 * m0, 0.f) + 1e-5f);
    float r1 = rsqrtf(fmaxf(q1 - m1 * m1, 0.f) + 1e-5f);
    float r2 = rsqrtf(fmaxf(q2 - m2 * m2, 0.f) + 1e-5f);

    float* ob = out + (size_t)b * Cn * HWn + p0;
    for (int c = 0; c < Cn; ++c) {
        float v0 = 0.f, v1 = 0.f, v2 = 0.f;
#pragma unroll
        for (int n = 0; n < N; ++n) {
            float w = sc[n * Cn + c];
            v0 += w * u0[n]; v1 += w * u1[n]; v2 += w * u2[n];
        }
        float A = sg[c], Bc = sb[c];
        float* o = ob + (size_t)c * HWn;
        o[0]   = (v0 - m0) * r0 * A + Bc;
        o[256] = (v1 - m1) * r1 * A + Bc;
        o[512] = (v2 - m2) * r2 * A + Bc;
    }
}

// ---------------------------------------------------------------------------
extern "C" void kernel_launch(void* const* d_in, const int* in_sizes, int n_in,
                              void* d_out, int out_size) {
    const float* feat   = (const float*)d_in[0];
    const float* iw1 = (const float*)d_in[1];
    const float* ib1 = (const float*)d_in[2];
    const float* iw2 = (const float*)d_in[3];
    const float* ib2 = (const float*)d_in[4];
    const float* ew1 = (const float*)d_in[5];
    const float* eb1 = (const float*)d_in[6];
    const float* ew2 = (const float*)d_in[7];
    const float* eb2 = (const float*)d_in[8];
    const float* cw1 = (const float*)d_in[9];
    const float* cb1 = (const float*)d_in[10];
    const float* cw2 = (const float*)d_in[11];
    const float* cb2 = (const float*)d_in[12];
    const float* rw1 = (const float*)d_in[13];
    const float* rb1 = (const float*)d_in[14];
    const float* rw2 = (const float*)d_in[15];
    const float* rb2 = (const float*)d_in[16];
    const float* lig = (const float*)d_in[17];
    const float* lib = (const float*)d_in[18];
    const float* leg = (const float*)d_in[19];
    const float* leb = (const float*)d_in[20];
    const float* lcg = (const float*)d_in[21];
    const float* lcb = (const float*)d_in[22];
    float* out = (float*)d_out;

    const size_t BR = (size_t)Bn * Cn * HWn;  // 9437184 elements per branch

    k_zero<<<144, 256>>>();
    k_basis<<<1, 64>>>(rw1, rb1, rw2, rb2);
    k_reduce<<<dim3(16, Bn), 256>>>(feat);
    k_hid<<<dim3(Bn, 3), 64>>>(iw1, ib1, ew1, eb1, cw1, cb1);
    k_coeff<<<dim3(NG, Bn), 256>>>(iw2, ib2, ew2, eb2, cw2, cb2);
    k_stats<<<dim3(3, Bn), 288>>>();
    k_uconv<<<dim3(NG, Bn), 256>>>();
    k_main<8><<<dim3(3, Bn), 256>>>(0, 0,  lig, lib, out);
    k_main<16><<<dim3(3, Bn), 256>>>(1, 8,  leg, leb, out + BR);
    k_main<16><<<dim3(3, Bn), 256>>>(2, 24, lcg, lcb, out + 2 * BR);
}